// round 4
// baseline (speedup 1.0000x reference)
#include <cuda_runtime.h>
#include <math.h>

#define NB 8
#define TT 8
#define CC 128
#define HH 64
#define WW 64
#define HW 4096

// ---------------- device scratch (no allocations allowed) ----------------
__device__ float g_M[NB * TT * CC];          // 8192
__device__ int   g_imp[TT * CC];             // 1024
__device__ float g_red[(size_t)NB * TT * 4 * HW];   // 4 MB: [nt][4][pix] avg_im,max_im,avg_sub,max_sub
__device__ float g_maps[(size_t)NB * 16 * HW];      // 2 MB: [n][i][pix], i<8 im, i>=8 sub

// ---------------- K1: M = mean_hw + max_hw ----------------
__global__ void k1_stats(const float* __restrict__ x) {
    int blk = blockIdx.x;  // n*T*C + t*C + c
    const float* p = x + (size_t)blk * HW;
    float s = 0.f, m = -INFINITY;
    for (int i = threadIdx.x; i < HW; i += 128) {
        float v = p[i];
        s += v;
        m = fmaxf(m, v);
    }
    for (int o = 16; o; o >>= 1) {
        s += __shfl_down_sync(0xffffffffu, s, o);
        m = fmaxf(m, __shfl_down_sync(0xffffffffu, m, o));
    }
    __shared__ float ss[4], sm[4];
    int w = threadIdx.x >> 5, l = threadIdx.x & 31;
    if (l == 0) { ss[w] = s; sm[w] = m; }
    __syncthreads();
    if (threadIdx.x == 0) {
        float S = ss[0] + ss[1] + ss[2] + ss[3];
        float Mx = fmaxf(fmaxf(sm[0], sm[1]), fmaxf(sm[2], sm[3]));
        g_M[blk] = S * (1.f / (float)HW) + Mx;
    }
}

// ---------------- K2: topk masks -> imp (XOR), single block ----------------
__global__ void k2_mask() {
    __shared__ float sM[NB * TT * CC];
    __shared__ unsigned char mch[TT * CC], mtm[TT * CC];
    int tid = threadIdx.x;
    for (int i = tid; i < NB * TT * CC; i += 1024) sM[i] = g_M[i];
    for (int i = tid; i < TT * CC; i += 1024) { mch[i] = 0; mtm[i] = 0; }
    __syncthreads();
    // channel top-64 per (n,t); union over n
    for (int it = tid; it < NB * TT * CC; it += 1024) {
        int c = it % CC; int t = (it / CC) % TT; int n = it / (CC * TT);
        const float* row = &sM[(n * TT + t) * CC];
        float v = row[c];
        int cnt = 0;
        for (int c2 = 0; c2 < CC; c2++) {
            float u = row[c2];
            cnt += (u > v) || (u == v && c2 < c);
        }
        if (cnt < 64) mch[t * CC + c] = 1;  // benign same-value byte races
    }
    // time top-4 per (n,c); union over n
    for (int it = tid; it < NB * CC * TT; it += 1024) {
        int t = it % TT; int c = (it / TT) % CC; int n = it / (TT * CC);
        float v = sM[(n * TT + t) * CC + c];
        int cnt = 0;
        for (int t2 = 0; t2 < TT; t2++) {
            float u = sM[(n * TT + t2) * CC + c];
            cnt += (u > v) || (u == v && t2 < t);
        }
        if (cnt < 4) mtm[t * CC + c] = 1;
    }
    __syncthreads();
    for (int i = tid; i < TT * CC; i += 1024) g_imp[i] = (int)(mch[i] ^ mtm[i]);
}

// ---------------- K3: masked channel reductions ----------------
__global__ void k3_reduce(const float* __restrict__ x) {
    int nt = blockIdx.y;  // n*8+t
    int t = nt & 7;
    int pix = blockIdx.x * 256 + threadIdx.x;  // 0..4095
    __shared__ int simp[CC];
    for (int i = threadIdx.x; i < CC; i += 256) simp[i] = g_imp[t * CC + i];
    __syncthreads();
    const float* p = x + (size_t)nt * CC * HW + pix;
    float s_all = 0.f, s_im = 0.f, mx_im = -INFINITY, mx_sub = -INFINITY;
#pragma unroll 4
    for (int c = 0; c < CC; c++) {
        float v = p[(size_t)c * HW];
        int ip = simp[c];
        float vi = ip ? v : 0.f;
        float vs = ip ? 0.f : v;
        s_all += v;
        s_im += vi;
        mx_im = fmaxf(mx_im, vi);
        mx_sub = fmaxf(mx_sub, vs);
    }
    float* r = g_red + (size_t)nt * 4 * HW + pix;
    r[0]          = s_im * (1.f / 64.f);          // mean/LAM = sum/64
    r[HW]         = mx_im;
    r[2 * HW]     = (s_all - s_im) * (1.f / 64.f);
    r[3 * HW]     = mx_sub;
}

// ---------------- K4: 2ch 3x3 conv + sigmoid -> maps ----------------
__global__ void k4_maps(const float* __restrict__ w1, const float* __restrict__ w2) {
    int nt = blockIdx.y; int n = nt >> 3, t = nt & 7;
    int pix = blockIdx.x * 256 + threadIdx.x;
    int y = pix >> 6, xq = pix & 63;
    __shared__ float sw1[18], sw2[18];
    if (threadIdx.x < 18) { sw1[threadIdx.x] = w1[threadIdx.x]; sw2[threadIdx.x] = w2[threadIdx.x]; }
    __syncthreads();
    const float* r = g_red + (size_t)nt * 4 * HW;
    float a_im = 0.f, a_sub = 0.f;
#pragma unroll
    for (int kh = 0; kh < 3; kh++) {
        int gy = y + kh - 1;
        if (gy < 0 || gy >= HH) continue;
#pragma unroll
        for (int kw = 0; kw < 3; kw++) {
            int gx = xq + kw - 1;
            if (gx < 0 || gx >= WW) continue;
            int o = gy * WW + gx;
            a_im  += sw1[kh * 3 + kw] * r[o]          + sw1[9 + kh * 3 + kw] * r[HW + o];
            a_sub += sw2[kh * 3 + kw] * r[2 * HW + o] + sw2[9 + kh * 3 + kw] * r[3 * HW + o];
        }
    }
    float im = 1.f / (1.f + expf(-a_im));
    float sb = 1.f / (1.f + expf(-a_sub));
    g_maps[((size_t)n * 16 + t) * HW + pix]     = im;
    g_maps[((size_t)n * 16 + t + 8) * HW + pix] = sb;
}

// ---------------- K5: fused htsa + 3D conv ----------------
#define THY 32
#define THX 32
#define VROW 34
#define VCOL 34
#define VPL (VROW * VCOL)  // 1156

__device__ __forceinline__ unsigned long long pack2(float v) {
    unsigned long long r;
    asm("mov.b64 %0, {%1, %1};" : "=l"(r) : "f"(v));
    return r;
}
__device__ __forceinline__ void ffma2(unsigned long long& d, unsigned long long a, unsigned long long b) {
    asm("fma.rn.f32x2 %0, %1, %2, %0;" : "+l"(d) : "l"(a), "l"(b));
}
__device__ __forceinline__ void unpack2(unsigned long long v, float& lo, float& hi) {
    asm("mov.b64 {%0, %1}, %2;" : "=f"(lo), "=f"(hi) : "l"(v));
}

extern __shared__ float smem5[];

__global__ void __launch_bounds__(256, 1) k5_conv(const float* __restrict__ x,
                                                  const float* __restrict__ wl,
                                                  float* __restrict__ out) {
    float* vs = smem5;               // 24 * VPL floats : v = map * x with halo
    float* ws = vs + 24 * VPL;       // 3456 floats: [i16][kd][k9][o]
    int* sisel = (int*)(ws + 3456);  // 24 ints

    int n = blockIdx.z;
    int d = blockIdx.y;
    int tileid = blockIdx.x;  // 0..3
    int y0 = (tileid >> 1) * THY, x0 = (tileid & 1) * THX;
    int tid = threadIdx.x;

    if (tid < 24) {
        int kd = tid / 8, t = tid % 8, dd = d + kd - 1;
        sisel[tid] = (dd >= 0 && dd < CC) ? (g_imp[t * CC + dd] ? t : t + 8) : 0;
    }
    // weights relayout: ws[((i16*3+kd)*9+k9)*8+o] = wl[(o*16+i16)*27 + kd*9 + k9]
    for (int i = tid; i < 3456; i += 256) {
        int o = i & 7; int q = i >> 3; int k9 = q % 9; q /= 9; int kd = q % 3; int i16 = q / 3;
        ws[i] = wl[(o * 16 + i16) * 27 + kd * 9 + k9];
    }
    __syncthreads();

    // stage vs = map[isel] * x  (spatial + d zero-padding)
    for (int idx = tid; idx < 24 * VPL; idx += 256) {
        int pl = idx / VPL; int rem = idx - pl * VPL;
        int yy = rem / VCOL, xx = rem - yy * VCOL;
        int kd = pl >> 3, t = pl & 7;
        int dd = d + kd - 1;
        int gy = y0 + yy - 1, gx = x0 + xx - 1;
        float v = 0.f;
        if (dd >= 0 && dd < CC && gy >= 0 && gy < HH && gx >= 0 && gx < WW) {
            int isel = sisel[pl];
            v = g_maps[((size_t)n * 16 + isel) * HW + gy * WW + gx] *
                x[(((size_t)(n * TT + t)) * CC + dd) * HW + gy * WW + gx];
        }
        vs[idx] = v;
    }
    __syncthreads();

    int lx = tid & 31;   // pixel x within tile
    int tg = tid >> 5;   // pixel-y group (4 rows per thread)

    unsigned long long acc[4][4];
#pragma unroll
    for (int pp = 0; pp < 4; pp++)
#pragma unroll
        for (int j = 0; j < 4; j++) acc[pp][j] = 0ull;

    for (int t = 0; t < 8; t++) {
#pragma unroll
        for (int kd = 0; kd < 3; kd++) {
            int isel = sisel[kd * 8 + t];
            const float* wb = ws + (isel * 3 + kd) * 72;
            const float* vb = vs + (kd * 8 + t) * VPL + (tg * 4) * VCOL + lx;
#pragma unroll
            for (int k9 = 0; k9 < 9; k9++) {
                int kh = k9 / 3, kw = k9 - kh * 3;
                const float* wp = wb + k9 * 8;
                unsigned long long w01 = *(const unsigned long long*)(wp + 0);
                unsigned long long w23 = *(const unsigned long long*)(wp + 2);
                unsigned long long w45 = *(const unsigned long long*)(wp + 4);
                unsigned long long w67 = *(const unsigned long long*)(wp + 6);
#pragma unroll
                for (int pp = 0; pp < 4; pp++) {
                    float v = vb[(pp + kh) * VCOL + kw];
                    unsigned long long vv = pack2(v);
                    ffma2(acc[pp][0], w01, vv);
                    ffma2(acc[pp][1], w23, vv);
                    ffma2(acc[pp][2], w45, vv);
                    ffma2(acc[pp][3], w67, vv);
                }
            }
        }
    }

    // store: out[((n*8+o)*128+d)*4096 + py*64+px]
    int px = x0 + lx;
#pragma unroll
    for (int pp = 0; pp < 4; pp++) {
        int py = y0 + tg * 4 + pp;
        size_t pb = (size_t)py * WW + px;
#pragma unroll
        for (int j = 0; j < 4; j++) {
            float lo, hi;
            unpack2(acc[pp][j], lo, hi);
            int o0 = 2 * j, o1 = 2 * j + 1;
            out[(((size_t)(n * 8 + o0)) * CC + d) * HW + pb] = lo;
            out[(((size_t)(n * 8 + o1)) * CC + d) * HW + pb] = hi;
        }
    }
}

// ---------------- launcher ----------------
extern "C" void kernel_launch(void* const* d_in, const int* in_sizes, int n_in,
                              void* d_out, int out_size) {
    const float* x  = (const float*)d_in[0];
    const float* w1 = (const float*)d_in[1];
    const float* w2 = (const float*)d_in[2];
    const float* wl = (const float*)d_in[3];
    float* out = (float*)d_out;

    k1_stats<<<NB * TT * CC, 128>>>(x);
    k2_mask<<<1, 1024>>>();
    {
        dim3 g(16, NB * TT);
        k3_reduce<<<g, 256>>>(x);
        k4_maps<<<g, 256>>>(w1, w2);
    }
    {
        int smem = (24 * VPL + 3456 + 32) * 4;  // ~125 KB
        cudaFuncSetAttribute(k5_conv, cudaFuncAttributeMaxDynamicSharedMemorySize, smem);
        dim3 g(4, CC, NB);
        k5_conv<<<g, 256, smem>>>(x, wl, out);
    }
}

// round 6
// speedup vs baseline: 2.4457x; 2.4457x over previous
#include <cuda_runtime.h>
#include <math.h>

#define NB 8
#define TT 8
#define CC 128
#define HH 64
#define WW 64
#define HW 4096

// ---------------- device scratch (no allocations allowed) ----------------
__device__ float g_M[NB * TT * CC];          // 8192
__device__ int   g_imp[TT * CC];             // 1024
__device__ float g_red[(size_t)NB * TT * 4 * HW];   // 4 MB
__device__ float g_maps[(size_t)NB * 16 * HW];      // 2 MB: [n][i][pix], i<8 im, i>=8 sub

// ---------------- K1: M = mean_hw + max_hw ----------------
__global__ void k1_stats(const float* __restrict__ x) {
    int blk = blockIdx.x;  // n*T*C + t*C + c
    const float* p = x + (size_t)blk * HW;
    float s = 0.f, m = -INFINITY;
    for (int i = threadIdx.x; i < HW; i += 128) {
        float v = p[i];
        s += v;
        m = fmaxf(m, v);
    }
    for (int o = 16; o; o >>= 1) {
        s += __shfl_down_sync(0xffffffffu, s, o);
        m = fmaxf(m, __shfl_down_sync(0xffffffffu, m, o));
    }
    __shared__ float ss[4], sm[4];
    int w = threadIdx.x >> 5, l = threadIdx.x & 31;
    if (l == 0) { ss[w] = s; sm[w] = m; }
    __syncthreads();
    if (threadIdx.x == 0) {
        float S = ss[0] + ss[1] + ss[2] + ss[3];
        float Mx = fmaxf(fmaxf(sm[0], sm[1]), fmaxf(sm[2], sm[3]));
        g_M[blk] = S * (1.f / (float)HW) + Mx;
    }
}

// ---------------- K2: topk masks -> imp (XOR), single block ----------------
__global__ void k2_mask() {
    __shared__ float sM[NB * TT * CC];
    __shared__ unsigned char mch[TT * CC], mtm[TT * CC];
    int tid = threadIdx.x;
    for (int i = tid; i < NB * TT * CC; i += 1024) sM[i] = g_M[i];
    for (int i = tid; i < TT * CC; i += 1024) { mch[i] = 0; mtm[i] = 0; }
    __syncthreads();
    for (int it = tid; it < NB * TT * CC; it += 1024) {
        int c = it % CC; int t = (it / CC) % TT; int n = it / (CC * TT);
        const float* row = &sM[(n * TT + t) * CC];
        float v = row[c];
        int cnt = 0;
        for (int c2 = 0; c2 < CC; c2++) {
            float u = row[c2];
            cnt += (u > v) || (u == v && c2 < c);
        }
        if (cnt < 64) mch[t * CC + c] = 1;
    }
    for (int it = tid; it < NB * CC * TT; it += 1024) {
        int t = it % TT; int c = (it / TT) % CC; int n = it / (TT * CC);
        float v = sM[(n * TT + t) * CC + c];
        int cnt = 0;
        for (int t2 = 0; t2 < TT; t2++) {
            float u = sM[(n * TT + t2) * CC + c];
            cnt += (u > v) || (u == v && t2 < t);
        }
        if (cnt < 4) mtm[t * CC + c] = 1;
    }
    __syncthreads();
    for (int i = tid; i < TT * CC; i += 1024) g_imp[i] = (int)(mch[i] ^ mtm[i]);
}

// ---------------- K3: masked channel reductions ----------------
__global__ void k3_reduce(const float* __restrict__ x) {
    int nt = blockIdx.y;
    int t = nt & 7;
    int pix = blockIdx.x * 256 + threadIdx.x;
    __shared__ int simp[CC];
    for (int i = threadIdx.x; i < CC; i += 256) simp[i] = g_imp[t * CC + i];
    __syncthreads();
    const float* p = x + (size_t)nt * CC * HW + pix;
    float s_all = 0.f, s_im = 0.f, mx_im = -INFINITY, mx_sub = -INFINITY;
#pragma unroll 4
    for (int c = 0; c < CC; c++) {
        float v = p[(size_t)c * HW];
        int ip = simp[c];
        float vi = ip ? v : 0.f;
        float vs = ip ? 0.f : v;
        s_all += v;
        s_im += vi;
        mx_im = fmaxf(mx_im, vi);
        mx_sub = fmaxf(mx_sub, vs);
    }
    float* r = g_red + (size_t)nt * 4 * HW + pix;
    r[0]          = s_im * (1.f / 64.f);
    r[HW]         = mx_im;
    r[2 * HW]     = (s_all - s_im) * (1.f / 64.f);
    r[3 * HW]     = mx_sub;
}

// ---------------- K4: 2ch 3x3 conv + sigmoid -> maps ----------------
__global__ void k4_maps(const float* __restrict__ w1, const float* __restrict__ w2) {
    int nt = blockIdx.y; int n = nt >> 3, t = nt & 7;
    int pix = blockIdx.x * 256 + threadIdx.x;
    int y = pix >> 6, xq = pix & 63;
    __shared__ float sw1[18], sw2[18];
    if (threadIdx.x < 18) { sw1[threadIdx.x] = w1[threadIdx.x]; sw2[threadIdx.x] = w2[threadIdx.x]; }
    __syncthreads();
    const float* r = g_red + (size_t)nt * 4 * HW;
    float a_im = 0.f, a_sub = 0.f;
#pragma unroll
    for (int kh = 0; kh < 3; kh++) {
        int gy = y + kh - 1;
        if (gy < 0 || gy >= HH) continue;
#pragma unroll
        for (int kw = 0; kw < 3; kw++) {
            int gx = xq + kw - 1;
            if (gx < 0 || gx >= WW) continue;
            int o = gy * WW + gx;
            a_im  += sw1[kh * 3 + kw] * r[o]          + sw1[9 + kh * 3 + kw] * r[HW + o];
            a_sub += sw2[kh * 3 + kw] * r[2 * HW + o] + sw2[9 + kh * 3 + kw] * r[3 * HW + o];
        }
    }
    float im = 1.f / (1.f + expf(-a_im));
    float sb = 1.f / (1.f + expf(-a_sub));
    g_maps[((size_t)n * 16 + t) * HW + pix]     = im;
    g_maps[((size_t)n * 16 + t + 8) * HW + pix] = sb;
}

// ---------------- K5: fused htsa + 3D conv, kd-phased for occupancy ----------------
#define THY 32
#define THX 32
#define VROW 34
#define VCOL 34
#define VPL (VROW * VCOL)  // 1156

__device__ __forceinline__ unsigned long long pack2(float v) {
    unsigned long long r;
    asm("mov.b64 %0, {%1, %1};" : "=l"(r) : "f"(v));
    return r;
}
__device__ __forceinline__ void ffma2(unsigned long long& d, unsigned long long a, unsigned long long b) {
    asm("fma.rn.f32x2 %0, %1, %2, %0;" : "+l"(d) : "l"(a), "l"(b));
}
__device__ __forceinline__ void unpack2(unsigned long long v, float& lo, float& hi) {
    asm("mov.b64 {%0, %1}, %2;" : "=f"(lo), "=f"(hi) : "l"(v));
}

extern __shared__ float smem5[];

__global__ void __launch_bounds__(256) k5_conv(const float* __restrict__ x,
                                               const float* __restrict__ wl,
                                               float* __restrict__ out) {
    float* vs = smem5;               // 8 * VPL floats : one kd phase of v = map * x (halo)
    float* ws = vs + 8 * VPL;        // 3456 floats: [i16][kd][k9][o]
    int* sisel = (int*)(ws + 3456);  // 24 ints

    int n = blockIdx.z;
    int d = blockIdx.y;
    int tileid = blockIdx.x;  // 0..3
    int y0 = (tileid >> 1) * THY, x0 = (tileid & 1) * THX;
    int tid = threadIdx.x;

    if (tid < 24) {
        int kd = tid / 8, t = tid % 8, dd = d + kd - 1;
        sisel[tid] = (dd >= 0 && dd < CC) ? (g_imp[t * CC + dd] ? t : t + 8) : 0;
    }
    // weights relayout: ws[((i16*3+kd)*9+k9)*8+o] = wl[(o*16+i16)*27 + kd*9 + k9]
    for (int i = tid; i < 3456; i += 256) {
        int o = i & 7; int q = i >> 3; int k9 = q % 9; q /= 9; int kd = q % 3; int i16 = q / 3;
        ws[i] = wl[(o * 16 + i16) * 27 + kd * 9 + k9];
    }

    int lx = tid & 31;   // pixel x within tile
    int tg = tid >> 5;   // pixel-y group (4 rows per thread)

    unsigned long long acc[4][4];
#pragma unroll
    for (int pp = 0; pp < 4; pp++)
#pragma unroll
        for (int j = 0; j < 4; j++) acc[pp][j] = 0ull;

    for (int kd = 0; kd < 3; kd++) {
        int dd = d + kd - 1;
        if (dd < 0 || dd >= CC) continue;   // block-uniform: skip dead phase entirely

        __syncthreads();  // protect vs (prev compute done / ws+sisel visible on first pass)

        // stage 8 t-planes of v = map[isel]*x for this dd
        const float* xb = x + ((size_t)n * TT * CC + dd) * HW;  // + t*CC*HW
        const float* mb = g_maps + (size_t)n * 16 * HW;
        for (int t = 0; t < 8; t++) {
            int isel = sisel[kd * 8 + t];
            const float* mp = mb + (size_t)isel * HW;
            const float* xp = xb + (size_t)t * CC * HW;
            float* vp = vs + t * VPL;
            for (int e = tid; e < VPL; e += 256) {
                int yy = e / VCOL, xx = e - yy * VCOL;
                int gy = y0 + yy - 1, gx = x0 + xx - 1;
                float v = 0.f;
                if (gy >= 0 && gy < HH && gx >= 0 && gx < WW) {
                    int o = gy * WW + gx;
                    v = mp[o] * xp[o];
                }
                vp[e] = v;
            }
        }
        __syncthreads();

        // accumulate this kd's contribution
        for (int t = 0; t < 8; t++) {
            int isel = sisel[kd * 8 + t];
            const float* wb = ws + (isel * 3 + kd) * 72;
            const float* vb = vs + t * VPL + (tg * 4) * VCOL + lx;
#pragma unroll
            for (int k9 = 0; k9 < 9; k9++) {
                int kh = k9 / 3, kw = k9 - kh * 3;
                const float* wp = wb + k9 * 8;
                unsigned long long w01 = *(const unsigned long long*)(wp + 0);
                unsigned long long w23 = *(const unsigned long long*)(wp + 2);
                unsigned long long w45 = *(const unsigned long long*)(wp + 4);
                unsigned long long w67 = *(const unsigned long long*)(wp + 6);
#pragma unroll
                for (int pp = 0; pp < 4; pp++) {
                    float v = vb[(pp + kh) * VCOL + kw];
                    unsigned long long vv = pack2(v);
                    ffma2(acc[pp][0], w01, vv);
                    ffma2(acc[pp][1], w23, vv);
                    ffma2(acc[pp][2], w45, vv);
                    ffma2(acc[pp][3], w67, vv);
                }
            }
        }
    }

    // store: out[((n*8+o)*128+d)*4096 + py*64+px]
    int px = x0 + lx;
#pragma unroll
    for (int pp = 0; pp < 4; pp++) {
        int py = y0 + tg * 4 + pp;
        size_t pb = (size_t)py * WW + px;
#pragma unroll
        for (int j = 0; j < 4; j++) {
            float lo, hi;
            unpack2(acc[pp][j], lo, hi);
            int o0 = 2 * j, o1 = 2 * j + 1;
            out[(((size_t)(n * 8 + o0)) * CC + d) * HW + pb] = lo;
            out[(((size_t)(n * 8 + o1)) * CC + d) * HW + pb] = hi;
        }
    }
}

// ---------------- launcher ----------------
extern "C" void kernel_launch(void* const* d_in, const int* in_sizes, int n_in,
                              void* d_out, int out_size) {
    const float* x  = (const float*)d_in[0];
    const float* w1 = (const float*)d_in[1];
    const float* w2 = (const float*)d_in[2];
    const float* wl = (const float*)d_in[3];
    float* out = (float*)d_out;

    k1_stats<<<NB * TT * CC, 128>>>(x);
    k2_mask<<<1, 1024>>>();
    {
        dim3 g(16, NB * TT);
        k3_reduce<<<g, 256>>>(x);
        k4_maps<<<g, 256>>>(w1, w2);
    }
    {
        int smem = (8 * VPL + 3456 + 32) * 4;  // ~51 KB -> 3 CTAs/SM
        cudaFuncSetAttribute(k5_conv, cudaFuncAttributeMaxDynamicSharedMemorySize, smem);
        dim3 g(4, CC, NB);
        k5_conv<<<g, 256, smem>>>(x, wl, out);
    }
}